// round 11
// baseline (speedup 1.0000x reference)
#include <cuda_runtime.h>
#include <cuda_fp16.h>
#include <math.h>
#include <stdint.h>

#define B_   8
#define CIN  64
#define COUT 32
#define HIN  128
#define WIN  128
#define HO   256
#define WO   256
#define ATT  16
#define KNUM 2
#define EPS  1e-5f
#define RATIO 0.49803921568627452f   // 127/255

typedef unsigned long long u64;
typedef unsigned int u32;

// Scratch device globals
__device__ float g_gap[B_ * CIN];                 // mean of upsampled x
// upsampled image, fp16, layout [b][g=ci/8][oy][ox][8ci] (uint4 per px-chunk)
__device__ __half g_xh[(size_t)B_ * CIN * HO * WO];
// folded per-sample weights, fp16, layout [b][q][co][ci]
__device__ __half g_w[B_ * 9 * COUT * CIN];
__device__ float g_bias[COUT];

// ---------------- warp-level MMA helpers (plain sm_103 PTX, sm_80+) --------
__device__ __forceinline__ u32 smem_to_u32(const void* p) {
    u32 a;
    asm("{ .reg .u64 t; cvta.to.shared.u64 t, %1; cvt.u32.u64 %0, t; }"
        : "=r"(a) : "l"(p));
    return a;
}
__device__ __forceinline__ void ldsm_x4(u32* r, u32 addr) {
    asm volatile("ldmatrix.sync.aligned.m8n8.x4.shared.b16 {%0,%1,%2,%3}, [%4];"
                 : "=r"(r[0]), "=r"(r[1]), "=r"(r[2]), "=r"(r[3]) : "r"(addr));
}
__device__ __forceinline__ void ldsm_x2(u32* r, u32 addr) {
    asm volatile("ldmatrix.sync.aligned.m8n8.x2.shared.b16 {%0,%1}, [%2];"
                 : "=r"(r[0]), "=r"(r[1]) : "r"(addr));
}
__device__ __forceinline__ void mma_fp16(float* c, const u32* a, const u32* b) {
    asm volatile(
        "mma.sync.aligned.m16n8k16.row.col.f32.f16.f16.f32 "
        "{%0,%1,%2,%3}, {%4,%5,%6,%7}, {%8,%9}, {%0,%1,%2,%3};"
        : "+f"(c[0]), "+f"(c[1]), "+f"(c[2]), "+f"(c[3])
        : "r"(a[0]), "r"(a[1]), "r"(a[2]), "r"(a[3]), "r"(b[0]), "r"(b[1]));
}

// ---------------------------------------------------------------------------
// K_gap: GAP of the virtual upsample via separable row weights R (no atomics)
// ---------------------------------------------------------------------------
__global__ void k_gap(const float* __restrict__ x)
{
    __shared__ float sR[HIN];
    __shared__ float red[256];
    int t = threadIdx.x;
    if (t < HIN) sR[t] = 0.0f;
    __syncthreads();
    if (t < HO) {
        float py = (float)t * RATIO;
        int   y0 = (int)py;
        float wy = py - (float)y0;
        int   y1 = min(y0 + 1, HIN - 1);
        atomicAdd(&sR[y0], 1.0f - wy);
        atomicAdd(&sR[y1], wy);
    }
    __syncthreads();
    int bc = blockIdx.x;
    const float* __restrict__ plane = x + (size_t)bc * HIN * WIN;
    float lsum = 0.0f;
    for (int idx = t; idx < HIN * WIN; idx += 256) {
        int y = idx >> 7, c = idx & 127;
        lsum += plane[idx] * sR[y] * sR[c];
    }
    red[t] = lsum;
    __syncthreads();
    for (int s = 128; s > 0; s >>= 1) {
        if (t < s) red[t] += red[t + s];
        __syncthreads();
    }
    if (t == 0) g_gap[bc] = red[0] * (1.0f / (float)(HO * WO));
}

// ---------------------------------------------------------------------------
// K1: bilinear x2 upsample -> fp16 planes. Two-phase: stage 2 source rows,
// row-interp once into sRI, then column lerp per output px.
// Block = (oy, g, b); thread = ox.
// ---------------------------------------------------------------------------
__global__ void __launch_bounds__(256) k_upsample(const float* __restrict__ x)
{
    __shared__ float sX[8][2][WIN];
    __shared__ float sRI[8][WIN];

    int oy = blockIdx.x;
    int g  = blockIdx.y;
    int b  = blockIdx.z;
    int ox = threadIdx.x;

    float py = (float)oy * RATIO;
    int   y0 = (int)py;
    float wy = py - (float)y0;
    int   y1 = min(y0 + 1, HIN - 1);

    const float* base = x + ((size_t)b * CIN + g * 8) * (HIN * WIN);
    for (int i = threadIdx.x; i < 8 * 2 * WIN; i += 256) {
        int k = i >> 8;
        int r = (i >> 7) & 1;
        int c = i & 127;
        sX[k][r][c] = __ldg(base + (size_t)k * (HIN * WIN) +
                            (r ? y1 : y0) * WIN + c);
    }
    __syncthreads();

    for (int i = threadIdx.x; i < 8 * WIN; i += 256) {
        int k = i >> 7, c = i & 127;
        sRI[k][c] = sX[k][0][c] * (1.0f - wy) + sX[k][1][c] * wy;
    }
    __syncthreads();

    float px = (float)ox * RATIO;
    int   x0 = (int)px;
    float wx = px - (float)x0;
    int   x1 = min(x0 + 1, WIN - 1);

    u32 hw[4];
    #pragma unroll
    for (int j = 0; j < 4; j++) {
        int k0 = 2 * j, k1 = 2 * j + 1;
        float va = sRI[k0][x0] * (1.0f - wx) + sRI[k0][x1] * wx;
        float vb = sRI[k1][x0] * (1.0f - wx) + sRI[k1][x1] * wx;
        u32 p = (u32)__half_as_ushort(__float2half(va));
        p |= (u32)__half_as_ushort(__float2half(vb)) << 16;
        hw[j] = p;
    }
    ((uint4*)g_xh)[((size_t)(b * 8 + g) * HO + oy) * WO + ox] =
        make_uint4(hw[0], hw[1], hw[2], hw[3]);
}

// ---------------------------------------------------------------------------
// K2: attention MLP + weight fold -> fp16 weights [b][q][co][ci]
// ---------------------------------------------------------------------------
__global__ void k_attention(
    const float* __restrict__ fc_w,
    const float* __restrict__ bna_g, const float* __restrict__ bna_b,
    const float* __restrict__ bna_m, const float* __restrict__ bna_v,
    const float* __restrict__ ch_w,  const float* __restrict__ ch_b,
    const float* __restrict__ fil_w, const float* __restrict__ fil_b,
    const float* __restrict__ sp_w,  const float* __restrict__ sp_b,
    const float* __restrict__ k_w,   const float* __restrict__ k_b,
    const float* __restrict__ weight,
    const float* __restrict__ bn_g,  const float* __restrict__ bn_b,
    const float* __restrict__ bn_m,  const float* __restrict__ bn_v)
{
    int b = blockIdx.x;
    int t = threadIdx.x;
    __shared__ float sh[ATT];
    __shared__ float sch[CIN];
    __shared__ float sfs[COUT];
    __shared__ float ssp[9];
    __shared__ float sraw[KNUM];
    __shared__ float skk[KNUM];

    if (t < ATT) {
        const float* g = g_gap + b * CIN;
        float acc = 0.0f;
        #pragma unroll
        for (int ci = 0; ci < CIN; ci++) acc += fc_w[t * CIN + ci] * g[ci];
        acc = (acc - bna_m[t]) * rsqrtf(bna_v[t] + EPS) * bna_g[t] + bna_b[t];
        sh[t] = fmaxf(acc, 0.0f);
    }
    __syncthreads();
    if (t < CIN) {
        float a = ch_b[t];
        #pragma unroll
        for (int j = 0; j < ATT; j++) a += ch_w[t * ATT + j] * sh[j];
        sch[t] = 1.0f / (1.0f + expf(-a));
    } else if (t < CIN + COUT) {
        int co = t - CIN;
        float a = fil_b[co];
        #pragma unroll
        for (int j = 0; j < ATT; j++) a += fil_w[co * ATT + j] * sh[j];
        float fil = 1.0f / (1.0f + expf(-a));
        sfs[co] = fil * bn_g[co] * rsqrtf(bn_v[co] + EPS);
    } else if (t < CIN + COUT + 9) {
        int q = t - CIN - COUT;
        float a = sp_b[q];
        #pragma unroll
        for (int j = 0; j < ATT; j++) a += sp_w[q * ATT + j] * sh[j];
        ssp[q] = 1.0f / (1.0f + expf(-a));
    } else if (t < CIN + COUT + 9 + KNUM) {
        int k = t - CIN - COUT - 9;
        float a = k_b[k];
        #pragma unroll
        for (int j = 0; j < ATT; j++) a += k_w[k * ATT + j] * sh[j];
        sraw[k] = a;
    }
    __syncthreads();
    if (t == 0) {
        float m  = fmaxf(sraw[0], sraw[1]);
        float e0 = expf(sraw[0] - m);
        float e1 = expf(sraw[1] - m);
        float inv = 1.0f / (e0 + e1);
        skk[0] = e0 * inv;
        skk[1] = e1 * inv;
    }
    __syncthreads();

    const int WSZ = COUT * CIN * 9;
    for (int idx = t; idx < WSZ; idx += blockDim.x) {
        int co  = idx / (CIN * 9);
        int rem = idx % (CIN * 9);
        int ci  = rem / 9;
        int q   = rem % 9;
        float w = skk[0] * weight[idx] + skk[1] * weight[WSZ + idx];
        w = w * ssp[q] * sch[ci] * sfs[co];
        g_w[(((size_t)b * 9 + q) * COUT + co) * CIN + ci] = __float2half(w);
    }
    if (b == 0 && t < COUT)
        g_bias[t] = bn_b[t] - bn_m[t] * bn_g[t] * rsqrtf(bn_v[t] + EPS);
}

// ---------------------------------------------------------------------------
// K3: implicit-GEMM conv (mma.sync m16n8k16 fp16, single pass).
// CTA: (b, 2 output rows x 128 cols). 8 warps; warp = 32 px x 32 cout
// (2 m16 tiles sharing B fragments -> 6 LDSM per 8 MMA).
// A smem: 4 rows x 130 px x 64 cin fp16 from materialized g_xh.
// B smem: 9 tap matrices 32x64 fp16. 103.4 KB -> 2 CTAs/SM.
// ---------------------------------------------------------------------------
#define AROWB 16640           // 130 * 128 bytes
#define OFF_B 0               // 9 * 4096 = 36864
#define OFF_A 36864
#define SMEM_TOTAL (OFF_A + 4 * AROWB)   // 103424

#define SWZC(byte, r) ((byte) ^ (((r) & 7) << 4))

__global__ void __launch_bounds__(256, 2)
k_conv(float* __restrict__ out)
{
    extern __shared__ char smem[];
    u32 sb = smem_to_u32(smem);
    int tid  = threadIdx.x;
    int w    = tid >> 5;
    int lane = tid & 31;
    int b    = blockIdx.z;
    int r0   = blockIdx.y * 2;
    int c0   = blockIdx.x * 128;

    // ---- fill B: 9 q x 32 n x 8 chunks ------------------------------------
    for (int i = tid; i < 2304; i += 256) {
        int q    = i / 256;
        int rem2 = i % 256;
        int n    = rem2 >> 3;
        int g    = rem2 & 7;
        uint4 v = *(const uint4*)(g_w +
            (((size_t)b * 9 + q) * COUT + n) * CIN + g * 8);
        *(uint4*)(smem + OFF_B + q * 4096 + n * 128 + SWZC(g * 16, n)) = v;
    }

    // ---- fill A from g_xh: 4 rows x 8 chunks x 130 px (p fastest) ---------
    const uint4* xh4 = (const uint4*)g_xh;
    for (int i = tid; i < 4 * 8 * 130; i += 256) {
        int row = i / (8 * 130);
        int rem = i % (8 * 130);
        int g   = rem / 130;
        int p   = rem % 130;
        int oy  = r0 - 1 + row;
        int oc  = c0 - 1 + p;
        uint4 v = make_uint4(0, 0, 0, 0);
        if ((unsigned)oy < (unsigned)HO && (unsigned)oc < (unsigned)WO)
            v = xh4[((size_t)(b * 8 + g) * HO + oy) * WO + oc];
        *(uint4*)(smem + OFF_A + row * AROWB + p * 128 + SWZC(g * 16, p)) = v;
    }
    __syncthreads();

    // ---- mainloop: 9 taps x 4 k-steps, 2 m-tiles share B fragments --------
    float acc[2][4][4];
    #pragma unroll
    for (int mt = 0; mt < 2; mt++)
        #pragma unroll
        for (int nt = 0; nt < 4; nt++)
            #pragma unroll
            for (int r = 0; r < 4; r++) acc[mt][nt][r] = 0.0f;

    int wrow = w >> 2;             // output row within tile (0..1)
    int wcol = (w & 3) * 32;       // col base within 128-tile

    #pragma unroll 1
    for (int q = 0; q < 9; q++) {
        int ky = q / 3, kx = q % 3;
        u32 arow  = sb + OFF_A + (wrow + ky) * AROWB;
        u32 bbase = sb + OFF_B + q * 4096;
        #pragma unroll
        for (int ks = 0; ks < 4; ks++) {
            int kb = ks * 32;                 // 16 fp16 = 32 bytes
            u32 bfr[4][2];
            #pragma unroll
            for (int nt = 0; nt < 4; nt++) {
                int n = nt * 8 + (lane & 7);
                u32 addr = bbase + n * 128 +
                           SWZC(kb + ((lane >> 3) & 1) * 16, n);
                ldsm_x2(bfr[nt], addr);
            }
            #pragma unroll
            for (int mt = 0; mt < 2; mt++) {
                int p = wcol + mt * 16 + (lane & 15) + kx;
                u32 addr = arow + p * 128 +
                           SWZC(kb + ((lane >> 4) ? 16 : 0), p);
                u32 afr[4];
                ldsm_x4(afr, addr);
                #pragma unroll
                for (int nt = 0; nt < 4; nt++)
                    mma_fp16(acc[mt][nt], afr, bfr[nt]);
            }
        }
    }

    // ---- epilogue: bias + exact-erf GELU ----------------------------------
    int row = r0 + wrow;
    #pragma unroll
    for (int mt = 0; mt < 2; mt++) {
        int colb = c0 + wcol + mt * 16 + (lane >> 2);
        #pragma unroll
        for (int nt = 0; nt < 4; nt++) {
            int co0 = nt * 8 + (lane & 3) * 2;
            float b0 = g_bias[co0];
            float b1 = g_bias[co0 + 1];
            #pragma unroll
            for (int r = 0; r < 4; r++) {
                int co = co0 + (r & 1);
                int cc = colb + ((r >> 1) ? 8 : 0);
                float v = acc[mt][nt][r] + ((r & 1) ? b1 : b0);
                out[(((size_t)b * COUT + co) * HO + row) * WO + cc] =
                    0.5f * v * (1.0f + erff(v * 0.70710678118654752f));
            }
        }
    }
}

// ---------------------------------------------------------------------------
extern "C" void kernel_launch(void* const* d_in, const int* in_sizes, int n_in,
                              void* d_out, int out_size)
{
    const float* x      = (const float*)d_in[0];
    const float* fc_w   = (const float*)d_in[1];
    const float* bna_g  = (const float*)d_in[2];
    const float* bna_b  = (const float*)d_in[3];
    const float* bna_m  = (const float*)d_in[4];
    const float* bna_v  = (const float*)d_in[5];
    const float* ch_w   = (const float*)d_in[6];
    const float* ch_b   = (const float*)d_in[7];
    const float* fil_w  = (const float*)d_in[8];
    const float* fil_b  = (const float*)d_in[9];
    const float* sp_w   = (const float*)d_in[10];
    const float* sp_b   = (const float*)d_in[11];
    const float* k_w    = (const float*)d_in[12];
    const float* k_b    = (const float*)d_in[13];
    const float* weight = (const float*)d_in[14];
    const float* bn_g   = (const float*)d_in[15];
    const float* bn_b   = (const float*)d_in[16];
    const float* bn_m   = (const float*)d_in[17];
    const float* bn_v   = (const float*)d_in[18];

    cudaFuncSetAttribute(k_conv, cudaFuncAttributeMaxDynamicSharedMemorySize,
                         SMEM_TOTAL);

    k_gap<<<B_ * CIN, 256>>>(x);
    k_upsample<<<dim3(HO, 8, B_), 256>>>(x);
    k_attention<<<B_, 256>>>(fc_w, bna_g, bna_b, bna_m, bna_v,
                             ch_w, ch_b, fil_w, fil_b, sp_w, sp_b, k_w, k_b,
                             weight, bn_g, bn_b, bn_m, bn_v);
    k_conv<<<dim3(WO / 128, HO / 2, B_), 256, SMEM_TOTAL>>>((float*)d_out);
}

// round 13
// speedup vs baseline: 1.4555x; 1.4555x over previous
#include <cuda_runtime.h>
#include <cuda_fp16.h>
#include <math.h>
#include <stdint.h>

#define B_   8
#define CIN  64
#define COUT 32
#define HIN  128
#define WIN  128
#define HO   256
#define WO   256
#define ATT  16
#define KNUM 2
#define EPS  1e-5f
#define RATIO 0.49803921568627452f   // 127/255

typedef unsigned long long u64;
typedef unsigned int u32;

// Scratch device globals
__device__ float g_gap[B_ * CIN];                 // mean of upsampled x
// upsampled image, fp16, layout [b][g=ci/8][oy][ox][8ci] (uint4 per px-chunk)
__device__ __half g_xh[(size_t)B_ * CIN * HO * WO];
// folded per-sample weights, fp16, layout [b][q][co][ci]
__device__ __half g_w[B_ * 9 * COUT * CIN];
__device__ float g_bias[COUT];

// ---------------- warp-level MMA helpers (plain sm_103 PTX, sm_80+) --------
__device__ __forceinline__ u32 smem_to_u32(const void* p) {
    u32 a;
    asm("{ .reg .u64 t; cvta.to.shared.u64 t, %1; cvt.u32.u64 %0, t; }"
        : "=r"(a) : "l"(p));
    return a;
}
__device__ __forceinline__ void ldsm_x4(u32* r, u32 addr) {
    asm volatile("ldmatrix.sync.aligned.m8n8.x4.shared.b16 {%0,%1,%2,%3}, [%4];"
                 : "=r"(r[0]), "=r"(r[1]), "=r"(r[2]), "=r"(r[3]) : "r"(addr));
}
__device__ __forceinline__ void ldsm_x2(u32* r, u32 addr) {
    asm volatile("ldmatrix.sync.aligned.m8n8.x2.shared.b16 {%0,%1}, [%2];"
                 : "=r"(r[0]), "=r"(r[1]) : "r"(addr));
}
__device__ __forceinline__ void mma_fp16(float* c, const u32* a, const u32* b) {
    asm volatile(
        "mma.sync.aligned.m16n8k16.row.col.f32.f16.f16.f32 "
        "{%0,%1,%2,%3}, {%4,%5,%6,%7}, {%8,%9}, {%0,%1,%2,%3};"
        : "+f"(c[0]), "+f"(c[1]), "+f"(c[2]), "+f"(c[3])
        : "r"(a[0]), "r"(a[1]), "r"(a[2]), "r"(a[3]), "r"(b[0]), "r"(b[1]));
}

// ---------------------------------------------------------------------------
// K_gap: GAP of the virtual upsample via separable row weights R
// ---------------------------------------------------------------------------
__global__ void k_gap(const float* __restrict__ x)
{
    __shared__ float sR[HIN];
    __shared__ float red[256];
    int t = threadIdx.x;
    if (t < HIN) sR[t] = 0.0f;
    __syncthreads();
    if (t < HO) {
        float py = (float)t * RATIO;
        int   y0 = (int)py;
        float wy = py - (float)y0;
        int   y1 = min(y0 + 1, HIN - 1);
        atomicAdd(&sR[y0], 1.0f - wy);
        atomicAdd(&sR[y1], wy);
    }
    __syncthreads();
    int bc = blockIdx.x;
    const float* __restrict__ plane = x + (size_t)bc * HIN * WIN;
    float lsum = 0.0f;
    for (int idx = t; idx < HIN * WIN; idx += 256) {
        int y = idx >> 7, c = idx & 127;
        lsum += plane[idx] * sR[y] * sR[c];
    }
    red[t] = lsum;
    __syncthreads();
    for (int s = 128; s > 0; s >>= 1) {
        if (t < s) red[t] += red[t + s];
        __syncthreads();
    }
    if (t == 0) g_gap[bc] = red[0] * (1.0f / (float)(HO * WO));
}

// ---------------------------------------------------------------------------
// K1: bilinear x2 upsample -> fp16 planes (two-phase: row-interp then col)
// ---------------------------------------------------------------------------
__global__ void __launch_bounds__(256) k_upsample(const float* __restrict__ x)
{
    __shared__ float sX[8][2][WIN];
    __shared__ float sRI[8][WIN];

    int oy = blockIdx.x;
    int g  = blockIdx.y;
    int b  = blockIdx.z;
    int ox = threadIdx.x;

    float py = (float)oy * RATIO;
    int   y0 = (int)py;
    float wy = py - (float)y0;
    int   y1 = min(y0 + 1, HIN - 1);

    const float* base = x + ((size_t)b * CIN + g * 8) * (HIN * WIN);
    for (int i = threadIdx.x; i < 8 * 2 * WIN; i += 256) {
        int k = i >> 8;
        int r = (i >> 7) & 1;
        int c = i & 127;
        sX[k][r][c] = __ldg(base + (size_t)k * (HIN * WIN) +
                            (r ? y1 : y0) * WIN + c);
    }
    __syncthreads();

    for (int i = threadIdx.x; i < 8 * WIN; i += 256) {
        int k = i >> 7, c = i & 127;
        sRI[k][c] = sX[k][0][c] * (1.0f - wy) + sX[k][1][c] * wy;
    }
    __syncthreads();

    float px = (float)ox * RATIO;
    int   x0 = (int)px;
    float wx = px - (float)x0;
    int   x1 = min(x0 + 1, WIN - 1);

    u32 hw[4];
    #pragma unroll
    for (int j = 0; j < 4; j++) {
        int k0 = 2 * j, k1 = 2 * j + 1;
        float va = sRI[k0][x0] * (1.0f - wx) + sRI[k0][x1] * wx;
        float vb = sRI[k1][x0] * (1.0f - wx) + sRI[k1][x1] * wx;
        u32 p = (u32)__half_as_ushort(__float2half(va));
        p |= (u32)__half_as_ushort(__float2half(vb)) << 16;
        hw[j] = p;
    }
    ((uint4*)g_xh)[((size_t)(b * 8 + g) * HO + oy) * WO + ox] =
        make_uint4(hw[0], hw[1], hw[2], hw[3]);
}

// ---------------------------------------------------------------------------
// K2: attention MLP + weight fold -> fp16 weights [b][q][co][ci]
// ---------------------------------------------------------------------------
__global__ void k_attention(
    const float* __restrict__ fc_w,
    const float* __restrict__ bna_g, const float* __restrict__ bna_b,
    const float* __restrict__ bna_m, const float* __restrict__ bna_v,
    const float* __restrict__ ch_w,  const float* __restrict__ ch_b,
    const float* __restrict__ fil_w, const float* __restrict__ fil_b,
    const float* __restrict__ sp_w,  const float* __restrict__ sp_b,
    const float* __restrict__ k_w,   const float* __restrict__ k_b,
    const float* __restrict__ weight,
    const float* __restrict__ bn_g,  const float* __restrict__ bn_b,
    const float* __restrict__ bn_m,  const float* __restrict__ bn_v)
{
    int b = blockIdx.x;
    int t = threadIdx.x;
    __shared__ float sh[ATT];
    __shared__ float sch[CIN];
    __shared__ float sfs[COUT];
    __shared__ float ssp[9];
    __shared__ float sraw[KNUM];
    __shared__ float skk[KNUM];

    if (t < ATT) {
        const float* g = g_gap + b * CIN;
        float acc = 0.0f;
        #pragma unroll
        for (int ci = 0; ci < CIN; ci++) acc += fc_w[t * CIN + ci] * g[ci];
        acc = (acc - bna_m[t]) * rsqrtf(bna_v[t] + EPS) * bna_g[t] + bna_b[t];
        sh[t] = fmaxf(acc, 0.0f);
    }
    __syncthreads();
    if (t < CIN) {
        float a = ch_b[t];
        #pragma unroll
        for (int j = 0; j < ATT; j++) a += ch_w[t * ATT + j] * sh[j];
        sch[t] = 1.0f / (1.0f + expf(-a));
    } else if (t < CIN + COUT) {
        int co = t - CIN;
        float a = fil_b[co];
        #pragma unroll
        for (int j = 0; j < ATT; j++) a += fil_w[co * ATT + j] * sh[j];
        float fil = 1.0f / (1.0f + expf(-a));
        sfs[co] = fil * bn_g[co] * rsqrtf(bn_v[co] + EPS);
    } else if (t < CIN + COUT + 9) {
        int q = t - CIN - COUT;
        float a = sp_b[q];
        #pragma unroll
        for (int j = 0; j < ATT; j++) a += sp_w[q * ATT + j] * sh[j];
        ssp[q] = 1.0f / (1.0f + expf(-a));
    } else if (t < CIN + COUT + 9 + KNUM) {
        int k = t - CIN - COUT - 9;
        float a = k_b[k];
        #pragma unroll
        for (int j = 0; j < ATT; j++) a += k_w[k * ATT + j] * sh[j];
        sraw[k] = a;
    }
    __syncthreads();
    if (t == 0) {
        float m  = fmaxf(sraw[0], sraw[1]);
        float e0 = expf(sraw[0] - m);
        float e1 = expf(sraw[1] - m);
        float inv = 1.0f / (e0 + e1);
        skk[0] = e0 * inv;
        skk[1] = e1 * inv;
    }
    __syncthreads();

    const int WSZ = COUT * CIN * 9;
    for (int idx = t; idx < WSZ; idx += blockDim.x) {
        int co  = idx / (CIN * 9);
        int rem = idx % (CIN * 9);
        int ci  = rem / 9;
        int q   = rem % 9;
        float w = skk[0] * weight[idx] + skk[1] * weight[WSZ + idx];
        w = w * ssp[q] * sch[ci] * sfs[co];
        g_w[(((size_t)b * 9 + q) * COUT + co) * CIN + ci] = __float2half(w);
    }
    if (b == 0 && t < COUT)
        g_bias[t] = bn_b[t] - bn_m[t] * bn_g[t] * rsqrtf(bn_v[t] + EPS);
}

// ---------------------------------------------------------------------------
// K3: implicit-GEMM conv, split-k across warp pairs.
// CTA: (b, 2 rows x 64 cols) = 128 px, same 70.6 KB smem as the R10 champion
// -> 3 CTAs/SM. 8 warps = 4 pixel-groups x 2 k-halves. Warp: 2 m16 tiles in
// one row (B fragments shared) x 32 cout x its 32-k half -> per k-step
// 2 ldsm_x4 + 4 ldsm_x2 + 8 MMA. Cross-k reduction through the (dead) B
// smem region, then bias + exact GELU.
// ---------------------------------------------------------------------------
#define AROWB 8448            // 66 * 128 bytes
#define OFF_B 0               // 9 * 4096 = 36864
#define OFF_A 36864
#define SMEM_TOTAL (OFF_A + 4 * AROWB)   // 70656

#define SWZC(byte, r) ((byte) ^ (((r) & 7) << 4))

__global__ void __launch_bounds__(256, 3)
k_conv(float* __restrict__ out)
{
    extern __shared__ char smem[];
    u32 sb = smem_to_u32(smem);
    int tid  = threadIdx.x;
    int w    = tid >> 5;
    int lane = tid & 31;
    int b    = blockIdx.z;
    int r0   = blockIdx.y * 2;
    int c0   = blockIdx.x * 64;

    int kh   = w >> 2;            // k-half (0: ci 0-31, 1: ci 32-63)
    int pg   = w & 3;             // pixel group
    int wrow = pg >> 1;           // row within tile (0..1)
    int wcol = (pg & 1) * 32;     // col base within 64-tile

    // ---- fill B: 9 q x 32 n x 8 chunks ------------------------------------
    for (int i = tid; i < 2304; i += 256) {
        int q    = i / 256;
        int rem2 = i % 256;
        int n    = rem2 >> 3;
        int g    = rem2 & 7;
        uint4 v = *(const uint4*)(g_w +
            (((size_t)b * 9 + q) * COUT + n) * CIN + g * 8);
        *(uint4*)(smem + OFF_B + q * 4096 + n * 128 + SWZC(g * 16, n)) = v;
    }

    // ---- fill A from g_xh: 4 rows x 8 chunks x 66 px ----------------------
    const uint4* xh4 = (const uint4*)g_xh;
    for (int i = tid; i < 4 * 8 * 66; i += 256) {
        int row = i / (8 * 66);
        int rem = i % (8 * 66);
        int g   = rem / 66;
        int p   = rem % 66;
        int oy  = r0 - 1 + row;
        int oc  = c0 - 1 + p;
        uint4 v = make_uint4(0, 0, 0, 0);
        if ((unsigned)oy < (unsigned)HO && (unsigned)oc < (unsigned)WO)
            v = xh4[((size_t)(b * 8 + g) * HO + oy) * WO + oc];
        *(uint4*)(smem + OFF_A + row * AROWB + p * 128 + SWZC(g * 16, p)) = v;
    }
    __syncthreads();

    // ---- mainloop: 9 taps x 2 k-steps (this warp's half) ------------------
    float acc[2][4][4];
    #pragma unroll
    for (int mt = 0; mt < 2; mt++)
        #pragma unroll
        for (int nt = 0; nt < 4; nt++)
            #pragma unroll
            for (int r = 0; r < 4; r++) acc[mt][nt][r] = 0.0f;

    #pragma unroll 1
    for (int q = 0; q < 9; q++) {
        int ky = q / 3, kx = q % 3;
        u32 arow  = sb + OFF_A + (wrow + ky) * AROWB;
        u32 bbase = sb + OFF_B + q * 4096;
        #pragma unroll
        for (int ks = 0; ks < 2; ks++) {
            int kb = (kh * 2 + ks) * 32;      // 16 fp16 = 32 bytes
            u32 bfr[4][2];
            #pragma unroll
            for (int nt = 0; nt < 4; nt++) {
                int n = nt * 8 + (lane & 7);
                u32 addr = bbase + n * 128 +
                           SWZC(kb + ((lane >> 3) & 1) * 16, n);
                ldsm_x2(bfr[nt], addr);
            }
            #pragma unroll
            for (int mt = 0; mt < 2; mt++) {
                int p = wcol + mt * 16 + (lane & 15) + kx;
                u32 addr = arow + p * 128 +
                           SWZC(kb + ((lane >> 4) ? 16 : 0), p);
                u32 afr[4];
                ldsm_x4(afr, addr);
                #pragma unroll
                for (int nt = 0; nt < 4; nt++)
                    mma_fp16(acc[mt][nt], afr, bfr[nt]);
            }
        }
    }

    // ---- cross-k reduction through smem (B region is dead now) ------------
    float* buf = (float*)(smem + OFF_B);
    __syncthreads();
    if (kh == 1) {
        #pragma unroll
        for (int mt = 0; mt < 2; mt++)
            #pragma unroll
            for (int nt = 0; nt < 4; nt++)
                #pragma unroll
                for (int r = 0; r < 4; r++)
                    buf[((((pg * 2 + mt) * 4 + nt) * 4 + r) * 32) + lane] =
                        acc[mt][nt][r];
    }
    __syncthreads();

    // ---- epilogue (kh==0 warps): add partner half, bias + exact GELU ------
    if (kh == 0) {
        int row = r0 + wrow;
        #pragma unroll
        for (int mt = 0; mt < 2; mt++) {
            int colb = c0 + wcol + mt * 16 + (lane >> 2);
            #pragma unroll
            for (int nt = 0; nt < 4; nt++) {
                int co0 = nt * 8 + (lane & 3) * 2;
                float b0 = g_bias[co0];
                float b1 = g_bias[co0 + 1];
                #pragma unroll
                for (int r = 0; r < 4; r++) {
                    float v = acc[mt][nt][r] +
                        buf[((((pg * 2 + mt) * 4 + nt) * 4 + r) * 32) + lane];
                    int co = co0 + (r & 1);
                    int cc = colb + ((r >> 1) ? 8 : 0);
                    v += (r & 1) ? b1 : b0;
                    out[(((size_t)b * COUT + co) * HO + row) * WO + cc] =
                        0.5f * v * (1.0f + erff(v * 0.70710678118654752f));
                }
            }
        }
    }
}

// ---------------------------------------------------------------------------
extern "C" void kernel_launch(void* const* d_in, const int* in_sizes, int n_in,
                              void* d_out, int out_size)
{
    const float* x      = (const float*)d_in[0];
    const float* fc_w   = (const float*)d_in[1];
    const float* bna_g  = (const float*)d_in[2];
    const float* bna_b  = (const float*)d_in[3];
    const float* bna_m  = (const float*)d_in[4];
    const float* bna_v  = (const float*)d_in[5];
    const float* ch_w   = (const float*)d_in[6];
    const float* ch_b   = (const float*)d_in[7];
    const float* fil_w  = (const float*)d_in[8];
    const float* fil_b  = (const float*)d_in[9];
    const float* sp_w   = (const float*)d_in[10];
    const float* sp_b   = (const float*)d_in[11];
    const float* k_w    = (const float*)d_in[12];
    const float* k_b    = (const float*)d_in[13];
    const float* weight = (const float*)d_in[14];
    const float* bn_g   = (const float*)d_in[15];
    const float* bn_b   = (const float*)d_in[16];
    const float* bn_m   = (const float*)d_in[17];
    const float* bn_v   = (const float*)d_in[18];

    cudaFuncSetAttribute(k_conv, cudaFuncAttributeMaxDynamicSharedMemorySize,
                         SMEM_TOTAL);

    k_gap<<<B_ * CIN, 256>>>(x);
    k_upsample<<<dim3(HO, 8, B_), 256>>>(x);
    k_attention<<<B_, 256>>>(fc_w, bna_g, bna_b, bna_m, bna_v,
                             ch_w, ch_b, fil_w, fil_b, sp_w, sp_b, k_w, k_b,
                             weight, bn_g, bn_b, bn_m, bn_v);
    k_conv<<<dim3(WO / 64, HO / 2, B_), 256, SMEM_TOTAL>>>((float*)d_out);
}